// round 1
// baseline (speedup 1.0000x reference)
#include <cuda_runtime.h>
#include <cstdint>

#define WARPS_PER_CTA 4
#define CTA_THREADS   (WARPS_PER_CTA * 32)

// ---- shared memory layout (in floats) ----
// weights region (per CTA), even offsets so float2 regions stay 8B-aligned
#define OFF_W1   0            // 72
#define OFF_B1   72           // 8
#define OFF_B2   80           // 16
#define OFF_BFC  96           // 1   (97..99 pad)
#define OFF_W2   100          // 16*73 = 1168 (stride-73 padded to avoid bank conflicts)
#define OFF_WFC  1268         // 784
#define WEIGHTS_FLOATS 2052   // rounded even

#define XS_F2    841          // 29*29 float2 (zero-padded top/left input)
#define Z1S_F2   1800         // 8 ch * 225 (15*15, zero-padded top/left)
#define WARP_STRIDE_FLOATS (XS_F2*2 + Z1S_F2*2 + 2)   // 5284
#define SMEM_FLOATS (WEIGHTS_FLOATS + WARPS_PER_CTA * WARP_STRIDE_FLOATS)
#define SMEM_BYTES  (SMEM_FLOATS * 4)                 // 92752

// packed fp32x2 FMA (sm_103a) — 2x fp32 FMA throughput vs scalar FFMA
__device__ __forceinline__ float2 ffma2(float2 a, float2 b, float2 c) {
    unsigned long long ua = *reinterpret_cast<unsigned long long*>(&a);
    unsigned long long ub = *reinterpret_cast<unsigned long long*>(&b);
    unsigned long long uc = *reinterpret_cast<unsigned long long*>(&c);
    unsigned long long ud;
    asm("fma.rn.f32x2 %0, %1, %2, %3;" : "=l"(ud) : "l"(ua), "l"(ub), "l"(uc));
    return *reinterpret_cast<float2*>(&ud);
}

__device__ __forceinline__ float2 bcast2(float v) { return make_float2(v, v); }

__device__ __forceinline__ float finish_prob(float z) {
    // softplus (stable) + 0.001, then 1 - exp(-r), clipped
    float sp = fmaxf(z, 0.0f) + log1pf(expf(-fabsf(z)));
    float r  = sp + 0.001f;
    float pr = -expm1f(-r);
    return fminf(fmaxf(pr, 1e-6f), 1.0f - 1e-6f);
}

__global__ __launch_bounds__(CTA_THREADS)
void diffsol_fused_kernel(const float* __restrict__ x,
                          const float* __restrict__ W1,
                          const float* __restrict__ b1,
                          const float* __restrict__ W2,
                          const float* __restrict__ b2,
                          const float* __restrict__ Wfc,
                          const float* __restrict__ bfc,
                          float* __restrict__ out,
                          int npairs) {
    extern __shared__ float smem[];
    float* sW1  = smem + OFF_W1;
    float* sb1  = smem + OFF_B1;
    float* sb2  = smem + OFF_B2;
    float* sbfc = smem + OFF_BFC;
    float* sW2  = smem + OFF_W2;
    float* sWfc = smem + OFF_WFC;

    const int tid = threadIdx.x;

    // ---- stage weights (whole CTA) ----
    for (int i = tid; i < 72;   i += CTA_THREADS) sW1[i] = W1[i];
    for (int i = tid; i < 8;    i += CTA_THREADS) sb1[i] = b1[i];
    for (int i = tid; i < 16;   i += CTA_THREADS) sb2[i] = b2[i];
    if (tid == 0) sbfc[0] = bfc[0];
    for (int i = tid; i < 1152; i += CTA_THREADS) sW2[(i / 72) * 73 + (i % 72)] = W2[i];
    for (int i = tid; i < 784;  i += CTA_THREADS) sWfc[i] = Wfc[i];
    __syncthreads();

    const int warp = tid >> 5;
    const int lane = tid & 31;
    const int g = blockIdx.x * WARPS_PER_CTA + warp;   // image-pair id
    if (g >= npairs) return;

    float* wbase = smem + WEIGHTS_FLOATS + warp * WARP_STRIDE_FLOATS;
    float2* xs  = reinterpret_cast<float2*>(wbase);            // [29][29]
    float2* z1s = reinterpret_cast<float2*>(wbase) + XS_F2;    // [8][15*15]

    const float* x0 = x + (size_t)(2 * g) * 784;
    const float* x1 = x0 + 784;

    // ---- stage input pair into padded smem ----
    for (int e = lane; e < 784; e += 32) {
        int r = e / 28, c = e - r * 28;
        xs[(r + 1) * 29 + (c + 1)] = make_float2(x0[e], x1[e]);
    }
    for (int z = lane; z < 57; z += 32) {                 // top row + left col zeros
        if (z < 29) xs[z] = make_float2(0.f, 0.f);
        else        xs[(z - 28) * 29] = make_float2(0.f, 0.f);
    }
    for (int z = lane; z < 232; z += 32) {                // z1 pads: 8ch * (15 + 14)
        int c = z / 29, r = z - c * 29;
        if (r < 15) z1s[c * 225 + r] = make_float2(0.f, 0.f);
        else        z1s[c * 225 + (r - 14) * 15] = make_float2(0.f, 0.f);
    }
    __syncwarp();

    const int cg = lane >> 3;   // 4 channel groups
    const int ps = lane & 7;    // 8 pixel slots

    // ---- conv1: 8ch x 14x14, lane = 2 channels x 25 pixel-iters, weights in regs ----
    {
        const int c0 = 2 * cg;
        float w1a[9], w1b[9];
        #pragma unroll
        for (int k = 0; k < 9; k++) { w1a[k] = sW1[c0 * 9 + k]; w1b[k] = sW1[(c0 + 1) * 9 + k]; }
        const float b1a = sb1[c0], b1b = sb1[c0 + 1];

        for (int t = 0; t < 25; t++) {
            int p = ps + 8 * t;
            int pe = p < 196 ? p : 195;
            int i = pe / 14, j = pe - i * 14;
            const float2* xb = xs + (2 * i) * 29 + 2 * j;
            float2 a0 = bcast2(b1a), a1 = bcast2(b1b);
            #pragma unroll
            for (int di = 0; di < 3; di++)
                #pragma unroll
                for (int dj = 0; dj < 3; dj++) {
                    float2 xv = xb[di * 29 + dj];
                    a0 = ffma2(xv, bcast2(w1a[di * 3 + dj]), a0);
                    a1 = ffma2(xv, bcast2(w1b[di * 3 + dj]), a1);
                }
            a0.x = fmaxf(a0.x, 0.f); a0.y = fmaxf(a0.y, 0.f);
            a1.x = fmaxf(a1.x, 0.f); a1.y = fmaxf(a1.y, 0.f);
            if (p < 196) {
                z1s[c0 * 225 + (i + 1) * 15 + (j + 1)]       = a0;
                z1s[(c0 + 1) * 225 + (i + 1) * 15 + (j + 1)] = a1;
            }
        }
    }
    __syncwarp();

    // ---- conv2 (16ch x 7x7) register-tiled: lane = 4 channels x 7 pixels ----
    const int cb = 4 * cg;
    int boff[7];
    #pragma unroll
    for (int t = 0; t < 7; t++) {
        int p = ps + 8 * t;
        int pe = p < 49 ? p : 48;
        int i = pe / 7, j = pe - i * 7;
        boff[t] = (2 * i) * 15 + 2 * j;
    }

    float2 acc[4][7];
    #pragma unroll
    for (int cc = 0; cc < 4; cc++) {
        float bb = sb2[cb + cc];
        #pragma unroll
        for (int t = 0; t < 7; t++) acc[cc][t] = bcast2(bb);
    }

    for (int ci = 0; ci < 8; ci++) {
        const float2* zb = z1s + ci * 225;
        #pragma unroll
        for (int r = 0; r < 9; r++) {
            const int di = r / 3, dj = r - 3 * (r / 3);
            float wv[4];
            #pragma unroll
            for (int cc = 0; cc < 4; cc++) wv[cc] = sW2[(cb + cc) * 73 + ci * 9 + r];
            float2 zv[7];
            #pragma unroll
            for (int t = 0; t < 7; t++) zv[t] = zb[boff[t] + di * 15 + dj];
            #pragma unroll
            for (int cc = 0; cc < 4; cc++) {
                float2 w2 = bcast2(wv[cc]);
                #pragma unroll
                for (int t = 0; t < 7; t++) acc[cc][t] = ffma2(zv[t], w2, acc[cc][t]);
            }
        }
    }

    // ---- FC: relu(z2) . Wfc, partial per lane then warp reduce ----
    float2 part = make_float2(0.f, 0.f);
    #pragma unroll
    for (int cc = 0; cc < 4; cc++)
        #pragma unroll
        for (int t = 0; t < 7; t++) {
            int p = ps + 8 * t;
            if (p < 49) {
                float wf = sWfc[(cb + cc) * 49 + p];
                float2 rz = make_float2(fmaxf(acc[cc][t].x, 0.f), fmaxf(acc[cc][t].y, 0.f));
                part = ffma2(rz, bcast2(wf), part);
            }
        }

    #pragma unroll
    for (int off = 16; off; off >>= 1) {
        part.x += __shfl_xor_sync(0xffffffffu, part.x, off);
        part.y += __shfl_xor_sync(0xffffffffu, part.y, off);
    }

    if (lane == 0) {
        float bb = sbfc[0];
        out[2 * g]     = finish_prob(part.x + bb);
        out[2 * g + 1] = finish_prob(part.y + bb);
    }
}

extern "C" void kernel_launch(void* const* d_in, const int* in_sizes, int n_in,
                              void* d_out, int out_size) {
    const float* x   = (const float*)d_in[0];
    const float* W1  = (const float*)d_in[1];
    const float* b1  = (const float*)d_in[2];
    const float* W2  = (const float*)d_in[3];
    const float* b2  = (const float*)d_in[4];
    const float* Wfc = (const float*)d_in[5];
    const float* bfc = (const float*)d_in[6];
    float* out = (float*)d_out;

    int nimg = in_sizes[0] / 784;
    int npairs = nimg / 2;
    int ctas = (npairs + WARPS_PER_CTA - 1) / WARPS_PER_CTA;

    cudaFuncSetAttribute(diffsol_fused_kernel,
                         cudaFuncAttributeMaxDynamicSharedMemorySize, SMEM_BYTES);
    diffsol_fused_kernel<<<ctas, CTA_THREADS, SMEM_BYTES>>>(
        x, W1, b1, W2, b2, Wfc, bfc, out, npairs);
}

// round 2
// speedup vs baseline: 1.3026x; 1.3026x over previous
#include <cuda_runtime.h>
#include <cuda_fp16.h>
#include <cstdint>

#define WARPS_PER_CTA 4
#define CTA_THREADS   (WARPS_PER_CTA * 32)

// ---- shared memory layout ----
// weights region (per CTA), fp32
#define OFF_W1   0            // 72
#define OFF_B1   72           // 8
#define OFF_B2   80           // 16
#define OFF_BFC  96           // 1  (pad to 100)
#define OFF_W2   100          // 16*73 = 1168 (stride-73 padded)
#define OFF_WFC  1268         // 784
#define WEIGHTS_FLOATS 2052

// per-warp activation buffers, half2 (one half2 = image pair)
#define XS_H2    841          // 29*29, zero-padded top/left input
#define Z1S_H2   1800         // 8 ch * 225 (15*15, zero-padded top/left)
#define WARP_H2  (XS_H2 + Z1S_H2 + 1)   // 2642 (x4B = 10568B/warp)
#define SMEM_FLOATS (WEIGHTS_FLOATS + WARPS_PER_CTA * WARP_H2)
#define SMEM_BYTES  (SMEM_FLOATS * 4)   // 50480 B -> 4 CTAs/SM

// packed fp32x2 FMA (sm_103a)
__device__ __forceinline__ float2 ffma2(float2 a, float2 b, float2 c) {
    unsigned long long ua = *reinterpret_cast<unsigned long long*>(&a);
    unsigned long long ub = *reinterpret_cast<unsigned long long*>(&b);
    unsigned long long uc = *reinterpret_cast<unsigned long long*>(&c);
    unsigned long long ud;
    asm("fma.rn.f32x2 %0, %1, %2, %3;" : "=l"(ud) : "l"(ua), "l"(ub), "l"(uc));
    return *reinterpret_cast<float2*>(&ud);
}
__device__ __forceinline__ float2 bcast2(float v) { return make_float2(v, v); }

__device__ __forceinline__ float finish_prob(float z) {
    float sp = fmaxf(z, 0.0f) + log1pf(expf(-fabsf(z)));
    float r  = sp + 0.001f;
    float pr = -expm1f(-r);
    return fminf(fmaxf(pr, 1e-6f), 1.0f - 1e-6f);
}

__global__ __launch_bounds__(CTA_THREADS, 4)
void diffsol_fused_kernel(const float* __restrict__ x,
                          const float* __restrict__ W1,
                          const float* __restrict__ b1,
                          const float* __restrict__ W2,
                          const float* __restrict__ b2,
                          const float* __restrict__ Wfc,
                          const float* __restrict__ bfc,
                          float* __restrict__ out,
                          int npairs) {
    extern __shared__ float smem[];
    float* sW1  = smem + OFF_W1;
    float* sb1  = smem + OFF_B1;
    float* sb2  = smem + OFF_B2;
    float* sbfc = smem + OFF_BFC;
    float* sW2  = smem + OFF_W2;
    float* sWfc = smem + OFF_WFC;

    const int tid = threadIdx.x;

    for (int i = tid; i < 72;   i += CTA_THREADS) sW1[i] = W1[i];
    for (int i = tid; i < 8;    i += CTA_THREADS) sb1[i] = b1[i];
    for (int i = tid; i < 16;   i += CTA_THREADS) sb2[i] = b2[i];
    if (tid == 0) sbfc[0] = bfc[0];
    for (int i = tid; i < 1152; i += CTA_THREADS) sW2[(i / 72) * 73 + (i % 72)] = W2[i];
    for (int i = tid; i < 784;  i += CTA_THREADS) sWfc[i] = Wfc[i];
    __syncthreads();

    const int warp = tid >> 5;
    const int lane = tid & 31;
    const int g = blockIdx.x * WARPS_PER_CTA + warp;   // image-pair id
    if (g >= npairs) return;

    __half2* wb  = reinterpret_cast<__half2*>(smem + WEIGHTS_FLOATS) + warp * WARP_H2;
    __half2* xs  = wb;             // [29][29]
    __half2* z1s = wb + XS_H2;     // [8][15*15]

    const float* x0 = x + (size_t)(2 * g) * 784;
    const float* x1 = x0 + 784;
    const __half2 hzero = __float2half2_rn(0.f);

    // ---- stage input pair into padded smem (half2 = image pair) ----
    for (int e = lane; e < 784; e += 32) {
        int r = e / 28, c = e - r * 28;
        xs[(r + 1) * 29 + (c + 1)] = __floats2half2_rn(x0[e], x1[e]);
    }
    for (int z = lane; z < 57; z += 32) {
        if (z < 29) xs[z] = hzero;
        else        xs[(z - 28) * 29] = hzero;
    }
    for (int z = lane; z < 232; z += 32) {     // z1 pads: 8ch * (15 + 14)
        int c = z / 29, r = z - c * 29;
        if (r < 15) z1s[c * 225 + r] = hzero;
        else        z1s[c * 225 + (r - 14) * 15] = hzero;
    }
    __syncwarp();

    // ---- conv1: lane = 4 channels x 16 pixel-lanes, weights in registers ----
    {
        const int chg = lane >> 4;          // 0..1
        const int s1  = lane & 15;
        const int c0  = 4 * chg;
        float w1r[4][9], b1r[4];
        #pragma unroll
        for (int cc = 0; cc < 4; cc++) {
            b1r[cc] = sb1[c0 + cc];
            #pragma unroll
            for (int k = 0; k < 9; k++) w1r[cc][k] = sW1[(c0 + cc) * 9 + k];
        }

        for (int t = 0; t < 13; t++) {
            int p = s1 + 16 * t;
            int pe = p < 196 ? p : 195;
            int i = pe / 14, j = pe - i * 14;
            const __half2* xb = xs + (2 * i) * 29 + 2 * j;
            float2 a[4];
            #pragma unroll
            for (int cc = 0; cc < 4; cc++) a[cc] = bcast2(b1r[cc]);
            #pragma unroll
            for (int di = 0; di < 3; di++)
                #pragma unroll
                for (int dj = 0; dj < 3; dj++) {
                    float2 xv = __half22float2(xb[di * 29 + dj]);
                    #pragma unroll
                    for (int cc = 0; cc < 4; cc++)
                        a[cc] = ffma2(xv, bcast2(w1r[cc][di * 3 + dj]), a[cc]);
                }
            if (p < 196) {
                #pragma unroll
                for (int cc = 0; cc < 4; cc++) {
                    __half2 h = __floats2half2_rn(a[cc].x, a[cc].y);
                    h = __hmax2(h, hzero);   // relu (exact: rounding is monotone)
                    z1s[(c0 + cc) * 225 + (i + 1) * 15 + (j + 1)] = h;
                }
            }
        }
    }
    __syncwarp();

    // ---- conv2 (16ch x 7x7): lane = 4 channels x 8 pixel-slots (7 iters) ----
    const int cg = lane >> 3;   // 4 channel groups
    const int ps = lane & 7;    // 8 pixel slots
    const int cb = 4 * cg;
    int boff[7];
    #pragma unroll
    for (int t = 0; t < 7; t++) {
        int p = ps + 8 * t;
        int pe = p < 49 ? p : 48;
        int i = pe / 7, j = pe - i * 7;
        boff[t] = (2 * i) * 15 + 2 * j;
    }

    float2 acc[4][7];
    #pragma unroll
    for (int cc = 0; cc < 4; cc++) {
        float bb = sb2[cb + cc];
        #pragma unroll
        for (int t = 0; t < 7; t++) acc[cc][t] = bcast2(bb);
    }

    for (int ci = 0; ci < 8; ci++) {
        const __half2* zb = z1s + ci * 225;
        #pragma unroll
        for (int r = 0; r < 9; r++) {
            const int di = r / 3, dj = r - 3 * (r / 3);
            float wv[4];
            #pragma unroll
            for (int cc = 0; cc < 4; cc++) wv[cc] = sW2[(cb + cc) * 73 + ci * 9 + r];
            float2 zv[7];
            #pragma unroll
            for (int t = 0; t < 7; t++) zv[t] = __half22float2(zb[boff[t] + di * 15 + dj]);
            #pragma unroll
            for (int cc = 0; cc < 4; cc++) {
                float2 w2 = bcast2(wv[cc]);
                #pragma unroll
                for (int t = 0; t < 7; t++) acc[cc][t] = ffma2(zv[t], w2, acc[cc][t]);
            }
        }
    }

    // ---- FC: relu(z2) . Wfc (fp32), warp reduce ----
    float2 part = make_float2(0.f, 0.f);
    #pragma unroll
    for (int cc = 0; cc < 4; cc++)
        #pragma unroll
        for (int t = 0; t < 7; t++) {
            int p = ps + 8 * t;
            if (p < 49) {
                float wf = sWfc[(cb + cc) * 49 + p];
                float2 rz = make_float2(fmaxf(acc[cc][t].x, 0.f), fmaxf(acc[cc][t].y, 0.f));
                part = ffma2(rz, bcast2(wf), part);
            }
        }

    #pragma unroll
    for (int off = 16; off; off >>= 1) {
        part.x += __shfl_xor_sync(0xffffffffu, part.x, off);
        part.y += __shfl_xor_sync(0xffffffffu, part.y, off);
    }

    if (lane == 0) {
        float bb = sbfc[0];
        out[2 * g]     = finish_prob(part.x + bb);
        out[2 * g + 1] = finish_prob(part.y + bb);
    }
}

extern "C" void kernel_launch(void* const* d_in, const int* in_sizes, int n_in,
                              void* d_out, int out_size) {
    const float* x   = (const float*)d_in[0];
    const float* W1  = (const float*)d_in[1];
    const float* b1  = (const float*)d_in[2];
    const float* W2  = (const float*)d_in[3];
    const float* b2  = (const float*)d_in[4];
    const float* Wfc = (const float*)d_in[5];
    const float* bfc = (const float*)d_in[6];
    float* out = (float*)d_out;

    int nimg = in_sizes[0] / 784;
    int npairs = nimg / 2;
    int ctas = (npairs + WARPS_PER_CTA - 1) / WARPS_PER_CTA;

    cudaFuncSetAttribute(diffsol_fused_kernel,
                         cudaFuncAttributeMaxDynamicSharedMemorySize, SMEM_BYTES);
    diffsol_fused_kernel<<<ctas, CTA_THREADS, SMEM_BYTES>>>(
        x, W1, b1, W2, b2, Wfc, bfc, out, npairs);
}

// round 7
// speedup vs baseline: 1.3104x; 1.0060x over previous
#include <cuda_runtime.h>
#include <cuda_fp16.h>
#include <cstdint>

#define WARPS_PER_CTA 4
#define CTA_THREADS   (WARPS_PER_CTA * 32)

// ---- weights region (floats): only the small ones stay in smem ----
#define OFF_W1   0            // 72
#define OFF_B1   72           // 8
#define OFF_B2   80           // 16
#define OFF_BFC  96           // 1 (pad to 100)
#define WEIGHTS_FLOATS 100

// per-warp activation buffers, half2 (one half2 = image pair)  [R2-proven]
#define XS_H2    841          // 29*29, zero-padded top/left input
#define Z1S_H2   1800         // 8 ch * 225 (15*15, zero-padded top/left)
#define WARP_H2  (XS_H2 + Z1S_H2 + 1)   // 2642 (x4B = 10568B/warp)
#define SMEM_FLOATS (WEIGHTS_FLOATS + WARPS_PER_CTA * WARP_H2)
#define SMEM_BYTES  (SMEM_FLOATS * 4)   // 42672 B -> 5 CTAs/SM

// packed fp32x2 FMA (sm_103a)
__device__ __forceinline__ float2 ffma2(float2 a, float2 b, float2 c) {
    unsigned long long ua = *reinterpret_cast<unsigned long long*>(&a);
    unsigned long long ub = *reinterpret_cast<unsigned long long*>(&b);
    unsigned long long uc = *reinterpret_cast<unsigned long long*>(&c);
    unsigned long long ud;
    asm("fma.rn.f32x2 %0, %1, %2, %3;" : "=l"(ud) : "l"(ua), "l"(ub), "l"(uc));
    return *reinterpret_cast<float2*>(&ud);
}
__device__ __forceinline__ float2 bcast2(float v) { return make_float2(v, v); }

__device__ __forceinline__ float finish_prob(float z) {
    float sp = fmaxf(z, 0.0f) + log1pf(expf(-fabsf(z)));
    float r  = sp + 0.001f;
    float pr = -expm1f(-r);
    return fminf(fmaxf(pr, 1e-6f), 1.0f - 1e-6f);
}

__global__ __launch_bounds__(CTA_THREADS, 5)
void diffsol_fused_kernel(const float* __restrict__ x,
                          const float* __restrict__ W1,
                          const float* __restrict__ b1,
                          const float* __restrict__ W2,
                          const float* __restrict__ b2,
                          const float* __restrict__ Wfc,
                          const float* __restrict__ bfc,
                          float* __restrict__ out,
                          int npairs) {
    extern __shared__ float smem[];
    float* sW1  = smem + OFF_W1;
    float* sb1  = smem + OFF_B1;
    float* sb2  = smem + OFF_B2;
    float* sbfc = smem + OFF_BFC;

    const int tid = threadIdx.x;

    for (int i = tid; i < 72;   i += CTA_THREADS) sW1[i] = W1[i];
    for (int i = tid; i < 8;    i += CTA_THREADS) sb1[i] = b1[i];
    for (int i = tid; i < 16;   i += CTA_THREADS) sb2[i] = b2[i];
    if (tid == 0) sbfc[0] = bfc[0];
    __syncthreads();

    const int warp = tid >> 5;
    const int lane = tid & 31;
    const int g = blockIdx.x * WARPS_PER_CTA + warp;   // image-pair id
    if (g >= npairs) return;

    __half2* wb  = reinterpret_cast<__half2*>(smem + WEIGHTS_FLOATS) + warp * WARP_H2;
    __half2* xs  = wb;             // [29][29]
    __half2* z1s = wb + XS_H2;     // [8][15*15]

    const float* x0 = x + (size_t)(2 * g) * 784;
    const float* x1 = x0 + 784;
    const __half2 hzero = __float2half2_rn(0.f);

    // ---- stage input pair into padded smem (half2 = image pair) ----
    for (int e = lane; e < 784; e += 32) {
        int r = e / 28, c = e - r * 28;
        xs[(r + 1) * 29 + (c + 1)] = __floats2half2_rn(x0[e], x1[e]);
    }
    for (int z = lane; z < 57; z += 32) {
        if (z < 29) xs[z] = hzero;
        else        xs[(z - 28) * 29] = hzero;
    }
    for (int z = lane; z < 232; z += 32) {     // z1 pads: 8ch * (15 + 14)
        int c = z / 29, r = z - c * 29;
        if (r < 15) z1s[c * 225 + r] = hzero;
        else        z1s[c * 225 + (r - 14) * 15] = hzero;
    }
    __syncwarp();

    // ---- conv1: lane = 4 channels x 16 pixel-lanes, weights in registers ----
    {
        const int chg = lane >> 4;          // 0..1
        const int s1  = lane & 15;
        const int c0  = 4 * chg;
        float w1r[4][9], b1r[4];
        #pragma unroll
        for (int cc = 0; cc < 4; cc++) {
            b1r[cc] = sb1[c0 + cc];
            #pragma unroll
            for (int k = 0; k < 9; k++) w1r[cc][k] = sW1[(c0 + cc) * 9 + k];
        }

        for (int t = 0; t < 13; t++) {
            int p = s1 + 16 * t;
            int pe = p < 196 ? p : 195;
            int i = pe / 14, j = pe - i * 14;
            const __half2* xb = xs + (2 * i) * 29 + 2 * j;
            float2 a[4];
            #pragma unroll
            for (int cc = 0; cc < 4; cc++) a[cc] = bcast2(b1r[cc]);
            #pragma unroll
            for (int di = 0; di < 3; di++)
                #pragma unroll
                for (int dj = 0; dj < 3; dj++) {
                    float2 xv = __half22float2(xb[di * 29 + dj]);
                    #pragma unroll
                    for (int cc = 0; cc < 4; cc++)
                        a[cc] = ffma2(xv, bcast2(w1r[cc][di * 3 + dj]), a[cc]);
                }
            if (p < 196) {
                #pragma unroll
                for (int cc = 0; cc < 4; cc++) {
                    __half2 h = __floats2half2_rn(a[cc].x, a[cc].y);
                    h = __hmax2(h, hzero);   // relu (monotone rounding)
                    z1s[(c0 + cc) * 225 + (i + 1) * 15 + (j + 1)] = h;
                }
            }
        }
    }
    __syncwarp();

    // ---- conv2 (16ch x 7x7): lane = 4 channels x 8 pixel-slots (7 iters) ----
    const int cg = lane >> 3;   // 4 channel groups
    const int ps = lane & 7;    // 8 pixel slots
    const int cb = 4 * cg;
    int boff[7];
    #pragma unroll
    for (int t = 0; t < 7; t++) {
        int p = ps + 8 * t;
        int pe = p < 49 ? p : 48;
        int i = pe / 7, j = pe - i * 7;
        boff[t] = (2 * i) * 15 + 2 * j;
    }

    float2 acc[4][7];
    #pragma unroll
    for (int cc = 0; cc < 4; cc++) {
        float bb = sb2[cb + cc];
        #pragma unroll
        for (int t = 0; t < 7; t++) acc[cc][t] = bcast2(bb);
    }

    for (int ci = 0; ci < 8; ci++) {
        const __half2* zb = z1s + ci * 225;
        #pragma unroll
        for (int r = 0; r < 9; r++) {
            const int di = r / 3, dj = r - 3 * (r / 3);
            float wv[4];
            #pragma unroll
            for (int cc = 0; cc < 4; cc++) wv[cc] = W2[(cb + cc) * 72 + ci * 9 + r];
            float2 zv[7];
            #pragma unroll
            for (int t = 0; t < 7; t++) zv[t] = __half22float2(zb[boff[t] + di * 15 + dj]);
            #pragma unroll
            for (int cc = 0; cc < 4; cc++) {
                float2 w2 = bcast2(wv[cc]);
                #pragma unroll
                for (int t = 0; t < 7; t++) acc[cc][t] = ffma2(zv[t], w2, acc[cc][t]);
            }
        }
    }

    // ---- FC: relu(z2) . Wfc (fp32, weights from gmem/L1), warp reduce ----
    float2 part = make_float2(0.f, 0.f);
    #pragma unroll
    for (int cc = 0; cc < 4; cc++)
        #pragma unroll
        for (int t = 0; t < 7; t++) {
            int p = ps + 8 * t;
            if (p < 49) {
                float wf = Wfc[(cb + cc) * 49 + p];
                float2 rz = make_float2(fmaxf(acc[cc][t].x, 0.f), fmaxf(acc[cc][t].y, 0.f));
                part = ffma2(rz, bcast2(wf), part);
            }
        }

    #pragma unroll
    for (int off = 16; off; off >>= 1) {
        part.x += __shfl_xor_sync(0xffffffffu, part.x, off);
        part.y += __shfl_xor_sync(0xffffffffu, part.y, off);
    }

    if (lane == 0) {
        float bb = sbfc[0];
        out[2 * g]     = finish_prob(part.x + bb);
        out[2 * g + 1] = finish_prob(part.y + bb);
    }
}

extern "C" void kernel_launch(void* const* d_in, const int* in_sizes, int n_in,
                              void* d_out, int out_size) {
    const float* x   = (const float*)d_in[0];
    const float* W1  = (const float*)d_in[1];
    const float* b1  = (const float*)d_in[2];
    const float* W2  = (const float*)d_in[3];
    const float* b2  = (const float*)d_in[4];
    const float* Wfc = (const float*)d_in[5];
    const float* bfc = (const float*)d_in[6];
    float* out = (float*)d_out;

    int nimg = in_sizes[0] / 784;
    int npairs = nimg / 2;
    int ctas = (npairs + WARPS_PER_CTA - 1) / WARPS_PER_CTA;

    cudaFuncSetAttribute(diffsol_fused_kernel,
                         cudaFuncAttributeMaxDynamicSharedMemorySize, SMEM_BYTES);
    diffsol_fused_kernel<<<ctas, CTA_THREADS, SMEM_BYTES>>>(
        x, W1, b1, W2, b2, Wfc, bfc, out, npairs);
}

// round 8
// speedup vs baseline: 1.3382x; 1.0212x over previous
#include <cuda_runtime.h>
#include <cuda_fp16.h>
#include <cstdint>

#define WARPS_PER_CTA 3
#define CTA_THREADS   (WARPS_PER_CTA * 32)

// ---- weights region (floats) ----
#define OFF_W1   0            // 72
#define OFF_B1   72           // 8
#define OFF_B2   80           // 16
#define OFF_BFC  96           // 1 (pad to 100)
#define OFF_W2T  100          // W2 transposed [72][16] = 1152 floats
#define WEIGHTS_FLOATS 1252   // even

// per-warp activation buffers, half2 (one half2 = image pair)  [R2/R7-proven]
#define XS_H2    841          // 29*29, zero-padded top/left input
#define Z1S_H2   1800         // 8 ch * 225 (15*15, zero-padded top/left)
#define WARP_H2  (XS_H2 + Z1S_H2 + 1)   // 2642 (x4B = 10568B/warp)
#define SMEM_FLOATS (WEIGHTS_FLOATS + WARPS_PER_CTA * WARP_H2)
#define SMEM_BYTES  (SMEM_FLOATS * 4)   // 36712 B -> 6 CTAs/SM (18 warps)

// packed fp32x2 FMA (sm_103a)
__device__ __forceinline__ float2 ffma2(float2 a, float2 b, float2 c) {
    unsigned long long ua = *reinterpret_cast<unsigned long long*>(&a);
    unsigned long long ub = *reinterpret_cast<unsigned long long*>(&b);
    unsigned long long uc = *reinterpret_cast<unsigned long long*>(&c);
    unsigned long long ud;
    asm("fma.rn.f32x2 %0, %1, %2, %3;" : "=l"(ud) : "l"(ua), "l"(ub), "l"(uc));
    return *reinterpret_cast<float2*>(&ud);
}
__device__ __forceinline__ float2 bcast2(float v) { return make_float2(v, v); }

__device__ __forceinline__ float finish_prob(float z) {
    float sp = fmaxf(z, 0.0f) + log1pf(expf(-fabsf(z)));
    float r  = sp + 0.001f;
    float pr = -expm1f(-r);
    return fminf(fmaxf(pr, 1e-6f), 1.0f - 1e-6f);
}

__global__ __launch_bounds__(CTA_THREADS, 6)
void diffsol_fused_kernel(const float* __restrict__ x,
                          const float* __restrict__ W1,
                          const float* __restrict__ b1,
                          const float* __restrict__ W2,
                          const float* __restrict__ b2,
                          const float* __restrict__ Wfc,
                          const float* __restrict__ bfc,
                          float* __restrict__ out,
                          int npairs) {
    extern __shared__ float smem[];
    float* sW1  = smem + OFF_W1;
    float* sb1  = smem + OFF_B1;
    float* sb2  = smem + OFF_B2;
    float* sbfc = smem + OFF_BFC;
    float* sW2t = smem + OFF_W2T;   // [72][16] transposed, conflict-free

    const int tid = threadIdx.x;

    for (int i = tid; i < 72;   i += CTA_THREADS) sW1[i] = W1[i];
    for (int i = tid; i < 8;    i += CTA_THREADS) sb1[i] = b1[i];
    for (int i = tid; i < 16;   i += CTA_THREADS) sb2[i] = b2[i];
    if (tid == 0) sbfc[0] = bfc[0];
    // W2 is [16 och][72]; store transposed: sW2t[k][och]
    for (int i = tid; i < 1152; i += CTA_THREADS) sW2t[(i % 72) * 16 + (i / 72)] = W2[i];
    __syncthreads();

    const int warp = tid >> 5;
    const int lane = tid & 31;
    const int g = blockIdx.x * WARPS_PER_CTA + warp;   // image-pair id
    if (g >= npairs) return;

    __half2* wb  = reinterpret_cast<__half2*>(smem + WEIGHTS_FLOATS) + warp * WARP_H2;
    __half2* xs  = wb;             // [29][29]
    __half2* z1s = wb + XS_H2;     // [8][15*15]

    const float* x0 = x + (size_t)(2 * g) * 784;
    const float* x1 = x0 + 784;
    const __half2 hzero = __float2half2_rn(0.f);

    // ---- stage input pair into padded smem (half2 = image pair) ----
    for (int e = lane; e < 784; e += 32) {
        int r = e / 28, c = e - r * 28;
        xs[(r + 1) * 29 + (c + 1)] = __floats2half2_rn(x0[e], x1[e]);
    }
    for (int z = lane; z < 57; z += 32) {
        if (z < 29) xs[z] = hzero;
        else        xs[(z - 28) * 29] = hzero;
    }
    for (int z = lane; z < 232; z += 32) {     // z1 pads: 8ch * (15 + 14)
        int c = z / 29, r = z - c * 29;
        if (r < 15) z1s[c * 225 + r] = hzero;
        else        z1s[c * 225 + (r - 14) * 15] = hzero;
    }
    __syncwarp();

    // ---- conv1: lane = 4 channels x 16 pixel-lanes, weights in registers ----
    {
        const int chg = lane >> 4;          // 0..1
        const int s1  = lane & 15;
        const int c0  = 4 * chg;
        float w1r[4][9], b1r[4];
        #pragma unroll
        for (int cc = 0; cc < 4; cc++) {
            b1r[cc] = sb1[c0 + cc];
            #pragma unroll
            for (int k = 0; k < 9; k++) w1r[cc][k] = sW1[(c0 + cc) * 9 + k];
        }

        for (int t = 0; t < 13; t++) {
            int p = s1 + 16 * t;
            int pe = p < 196 ? p : 195;
            int i = pe / 14, j = pe - i * 14;
            const __half2* xb = xs + (2 * i) * 29 + 2 * j;
            float2 a[4];
            #pragma unroll
            for (int cc = 0; cc < 4; cc++) a[cc] = bcast2(b1r[cc]);
            #pragma unroll
            for (int di = 0; di < 3; di++)
                #pragma unroll
                for (int dj = 0; dj < 3; dj++) {
                    float2 xv = __half22float2(xb[di * 29 + dj]);
                    #pragma unroll
                    for (int cc = 0; cc < 4; cc++)
                        a[cc] = ffma2(xv, bcast2(w1r[cc][di * 3 + dj]), a[cc]);
                }
            if (p < 196) {
                #pragma unroll
                for (int cc = 0; cc < 4; cc++) {
                    __half2 h = __floats2half2_rn(a[cc].x, a[cc].y);
                    h = __hmax2(h, hzero);   // relu (monotone rounding)
                    z1s[(c0 + cc) * 225 + (i + 1) * 15 + (j + 1)] = h;
                }
            }
        }
    }
    __syncwarp();

    // ---- conv2 (16ch x 7x7): lane = 4 channels x 8 pixel-slots (7 iters) ----
    const int cg = lane >> 3;   // 4 channel groups
    const int ps = lane & 7;    // 8 pixel slots
    const int cb = 4 * cg;
    int boff[7];
    #pragma unroll
    for (int t = 0; t < 7; t++) {
        int p = ps + 8 * t;
        int pe = p < 49 ? p : 48;
        int i = pe / 7, j = pe - i * 7;
        boff[t] = (2 * i) * 15 + 2 * j;
    }

    float2 acc[4][7];
    #pragma unroll
    for (int cc = 0; cc < 4; cc++) {
        float bb = sb2[cb + cc];
        #pragma unroll
        for (int t = 0; t < 7; t++) acc[cc][t] = bcast2(bb);
    }

    for (int ci = 0; ci < 8; ci++) {
        const __half2* zb = z1s + ci * 225;
        #pragma unroll
        for (int r = 0; r < 9; r++) {
            const int di = r / 3, dj = r - 3 * (r / 3);
            const float* wrow = sW2t + (ci * 9 + r) * 16;
            float wv[4];
            #pragma unroll
            for (int cc = 0; cc < 4; cc++) wv[cc] = wrow[cb + cc];
            float2 zv[7];
            #pragma unroll
            for (int t = 0; t < 7; t++) zv[t] = __half22float2(zb[boff[t] + di * 15 + dj]);
            #pragma unroll
            for (int cc = 0; cc < 4; cc++) {
                float2 w2 = bcast2(wv[cc]);
                #pragma unroll
                for (int t = 0; t < 7; t++) acc[cc][t] = ffma2(zv[t], w2, acc[cc][t]);
            }
        }
    }

    // ---- FC: relu(z2) . Wfc (fp32, weights from gmem/L1), warp reduce ----
    float2 part = make_float2(0.f, 0.f);
    #pragma unroll
    for (int cc = 0; cc < 4; cc++)
        #pragma unroll
        for (int t = 0; t < 7; t++) {
            int p = ps + 8 * t;
            if (p < 49) {
                float wf = Wfc[(cb + cc) * 49 + p];
                float2 rz = make_float2(fmaxf(acc[cc][t].x, 0.f), fmaxf(acc[cc][t].y, 0.f));
                part = ffma2(rz, bcast2(wf), part);
            }
        }

    #pragma unroll
    for (int off = 16; off; off >>= 1) {
        part.x += __shfl_xor_sync(0xffffffffu, part.x, off);
        part.y += __shfl_xor_sync(0xffffffffu, part.y, off);
    }

    if (lane == 0) {
        float bb = sbfc[0];
        out[2 * g]     = finish_prob(part.x + bb);
        out[2 * g + 1] = finish_prob(part.y + bb);
    }
}

extern "C" void kernel_launch(void* const* d_in, const int* in_sizes, int n_in,
                              void* d_out, int out_size) {
    const float* x   = (const float*)d_in[0];
    const float* W1  = (const float*)d_in[1];
    const float* b1  = (const float*)d_in[2];
    const float* W2  = (const float*)d_in[3];
    const float* b2  = (const float*)d_in[4];
    const float* Wfc = (const float*)d_in[5];
    const float* bfc = (const float*)d_in[6];
    float* out = (float*)d_out;

    int nimg = in_sizes[0] / 784;
    int npairs = nimg / 2;
    int ctas = (npairs + WARPS_PER_CTA - 1) / WARPS_PER_CTA;

    cudaFuncSetAttribute(diffsol_fused_kernel,
                         cudaFuncAttributeMaxDynamicSharedMemorySize, SMEM_BYTES);
    diffsol_fused_kernel<<<ctas, CTA_THREADS, SMEM_BYTES>>>(
        x, W1, b1, W2, b2, Wfc, bfc, out, npairs);
}

// round 9
// speedup vs baseline: 1.4010x; 1.0469x over previous
#include <cuda_runtime.h>
#include <cstdint>

#define WARPS_PER_CTA 3
#define CTA_THREADS   (WARPS_PER_CTA * 32)

// ---- smem layout (u32 units) ----
// W2 transposed [72][16] fp32 (conflict-free float4 reads)
#define OFF_W2T     0
#define W2T_U32     1152
// per-warp: xs bf16x2[29][29]+1 pad = 842 ; z1 bf16x2[8][15][16] = 1920
#define XS_U32      842
#define Z1_U32      1920
#define WARP_U32    (XS_U32 + Z1_U32)     // 2762 (even)
#define SMEM_U32    (W2T_U32 + WARPS_PER_CTA * WARP_U32)
#define SMEM_BYTES  (SMEM_U32 * 4)        // 37752 B -> 6 CTAs/SM (18 warps)

// packed fp32x2 FMA (sm_103a)
__device__ __forceinline__ float2 ffma2(float2 a, float2 b, float2 c) {
    unsigned long long ua = *reinterpret_cast<unsigned long long*>(&a);
    unsigned long long ub = *reinterpret_cast<unsigned long long*>(&b);
    unsigned long long uc = *reinterpret_cast<unsigned long long*>(&c);
    unsigned long long ud;
    asm("fma.rn.f32x2 %0, %1, %2, %3;" : "=l"(ud) : "l"(ua), "l"(ub), "l"(uc));
    return *reinterpret_cast<float2*>(&ud);
}
__device__ __forceinline__ float2 bcast2(float v) { return make_float2(v, v); }

// bf16x2 pack/unpack: no slow F2F — F2FP (fma/alu class) and SHF/LOP3 (alu)
__device__ __forceinline__ uint32_t pack_bf2(float lo, float hi) {
    uint32_t r;
    asm("cvt.rn.satfinite.bf16x2.f32 %0, %1, %2;" : "=r"(r) : "f"(hi), "f"(lo));
    return r;   // bits[15:0] = bf16(lo), bits[31:16] = bf16(hi)
}
__device__ __forceinline__ float2 unpack_bf2(uint32_t u) {
    float2 f;
    f.x = __uint_as_float(u << 16);
    f.y = __uint_as_float(u & 0xFFFF0000u);
    return f;
}

__device__ __forceinline__ float finish_prob(float z) {
    float sp = fmaxf(z, 0.0f) + log1pf(expf(-fabsf(z)));
    float r  = sp + 0.001f;
    float pr = -expm1f(-r);
    return fminf(fmaxf(pr, 1e-6f), 1.0f - 1e-6f);
}

__global__ __launch_bounds__(CTA_THREADS, 6)
void diffsol_fused_kernel(const float* __restrict__ x,
                          const float* __restrict__ W1,
                          const float* __restrict__ b1,
                          const float* __restrict__ W2,
                          const float* __restrict__ b2,
                          const float* __restrict__ Wfc,
                          const float* __restrict__ bfc,
                          float* __restrict__ out,
                          int npairs) {
    extern __shared__ uint32_t smem[];
    float* sW2t = reinterpret_cast<float*>(smem + OFF_W2T);   // [72][16]

    const int tid = threadIdx.x;

    // stage W2 transposed: sW2t[k][och] = W2[och][k]
    for (int i = tid; i < 1152; i += CTA_THREADS)
        sW2t[(i % 72) * 16 + (i / 72)] = W2[i];
    __syncthreads();

    const int warp = tid >> 5;
    const int lane = tid & 31;
    const int g = blockIdx.x * WARPS_PER_CTA + warp;   // image-pair id
    if (g >= npairs) return;

    uint32_t* wb  = smem + W2T_U32 + warp * WARP_U32;
    uint32_t* xs  = wb;             // [29][29] bf16x2, zero-pad top/left
    uint32_t* z1s = wb + XS_U32;    // [8][15][16] bf16x2, zero-pad top/left row/col

    const float* x0 = x + (size_t)(2 * g) * 784;
    const float* x1 = x0 + 784;

    // ---- stage input pair into padded xs ----
    for (int e = lane; e < 784; e += 32) {
        int r = e / 28, c = e - r * 28;
        xs[(r + 1) * 29 + (c + 1)] = pack_bf2(x0[e], x1[e]);
    }
    for (int z = lane; z < 57; z += 32) {                 // top row + left col zeros
        if (z < 29) xs[z] = 0u;
        else        xs[(z - 28) * 29] = 0u;
    }
    // z1 zero pads: per channel row 0 (16) + col 0 of rows 1..14 (14) = 30; x8 = 240
    for (int z = lane; z < 240; z += 32) {
        int ch = z / 30, q = z - ch * 30;
        if (q < 16) z1s[ch * 240 + q] = 0u;
        else        z1s[ch * 240 + (q - 15) * 16] = 0u;
    }
    __syncwarp();

    // ---- conv1: lane = 4 channels x 16 pixel-lanes, weights from gmem (once) ----
    {
        const int chg = lane >> 4;          // 0..1
        const int s1  = lane & 15;
        const int c0  = 4 * chg;
        float w1r[4][9], b1r[4];
        #pragma unroll
        for (int cc = 0; cc < 4; cc++) {
            b1r[cc] = b1[c0 + cc];
            #pragma unroll
            for (int k = 0; k < 9; k++) w1r[cc][k] = W1[(c0 + cc) * 9 + k];
        }

        for (int t = 0; t < 13; t++) {
            int p = s1 + 16 * t;
            int pe = p < 196 ? p : 195;
            int i = pe / 14, j = pe - i * 14;
            const uint32_t* xb = xs + (2 * i) * 29 + 2 * j;
            float2 a[4];
            #pragma unroll
            for (int cc = 0; cc < 4; cc++) a[cc] = bcast2(b1r[cc]);
            #pragma unroll
            for (int di = 0; di < 3; di++)
                #pragma unroll
                for (int dj = 0; dj < 3; dj++) {
                    float2 xv = unpack_bf2(xb[di * 29 + dj]);
                    #pragma unroll
                    for (int cc = 0; cc < 4; cc++)
                        a[cc] = ffma2(xv, bcast2(w1r[cc][di * 3 + dj]), a[cc]);
                }
            if (p < 196) {
                #pragma unroll
                for (int cc = 0; cc < 4; cc++) {
                    float lo = fmaxf(a[cc].x, 0.f);
                    float hi = fmaxf(a[cc].y, 0.f);
                    z1s[(c0 + cc) * 240 + (i + 1) * 16 + (j + 1)] = pack_bf2(lo, hi);
                }
            }
        }
    }
    __syncwarp();

    // ---- conv2 (16ch x 7x7): lane = 4 channel-groups x 8 pixel slots ----
    const int cg = lane >> 3;
    const int ps = lane & 7;
    const int cb = 4 * cg;
    int boff[7];
    #pragma unroll
    for (int t = 0; t < 7; t++) {
        int p = ps + 8 * t;
        int pe = p < 49 ? p : 48;
        int i = pe / 7, j = pe - i * 7;
        boff[t] = (2 * i) * 16 + 2 * j;   // padded z1: taps rows 2i+di, cols 2j+dj
    }

    float2 acc[4][7];
    #pragma unroll
    for (int cc = 0; cc < 4; cc++) {
        float bb = b2[cb + cc];
        #pragma unroll
        for (int t = 0; t < 7; t++) acc[cc][t] = bcast2(bb);
    }

    const float4* W2T4 = reinterpret_cast<const float4*>(sW2t);
    for (int ci = 0; ci < 8; ci++) {
        const uint32_t* zb = z1s + ci * 240;
        const int wk = ci * 9;
        #pragma unroll
        for (int di = 0; di < 3; di++) {
            // weights for 3 dj taps x 4 och: three LDS.128
            float4 wd0 = W2T4[(wk + di * 3 + 0) * 4 + cg];
            float4 wd1 = W2T4[(wk + di * 3 + 1) * 4 + cg];
            float4 wd2 = W2T4[(wk + di * 3 + 2) * 4 + cg];
            float w0[4] = {wd0.x, wd0.y, wd0.z, wd0.w};
            float w1[4] = {wd1.x, wd1.y, wd1.z, wd1.w};
            float w2[4] = {wd2.x, wd2.y, wd2.z, wd2.w};
            #pragma unroll
            for (int t = 0; t < 7; t++) {
                const uint32_t* zp = zb + boff[t] + di * 16;
                uint2 pr = *reinterpret_cast<const uint2*>(zp);  // taps dj=0,1 (8B aligned)
                uint32_t p2 = zp[2];                             // tap dj=2
                float2 z0 = unpack_bf2(pr.x);
                float2 z1v = unpack_bf2(pr.y);
                float2 z2v = unpack_bf2(p2);
                #pragma unroll
                for (int cc = 0; cc < 4; cc++) {
                    acc[cc][t] = ffma2(z0,  bcast2(w0[cc]), acc[cc][t]);
                    acc[cc][t] = ffma2(z1v, bcast2(w1[cc]), acc[cc][t]);
                    acc[cc][t] = ffma2(z2v, bcast2(w2[cc]), acc[cc][t]);
                }
            }
        }
    }

    // ---- FC: relu(z2) . Wfc (weights from gmem/L1), warp reduce ----
    float2 part = make_float2(0.f, 0.f);
    #pragma unroll
    for (int cc = 0; cc < 4; cc++)
        #pragma unroll
        for (int t = 0; t < 7; t++) {
            int p = ps + 8 * t;
            if (p < 49) {
                float wf = Wfc[(cb + cc) * 49 + p];
                float2 rz = make_float2(fmaxf(acc[cc][t].x, 0.f), fmaxf(acc[cc][t].y, 0.f));
                part = ffma2(rz, bcast2(wf), part);
            }
        }

    #pragma unroll
    for (int off = 16; off; off >>= 1) {
        part.x += __shfl_xor_sync(0xffffffffu, part.x, off);
        part.y += __shfl_xor_sync(0xffffffffu, part.y, off);
    }

    if (lane == 0) {
        float bb = bfc[0];
        out[2 * g]     = finish_prob(part.x + bb);
        out[2 * g + 1] = finish_prob(part.y + bb);
    }
}

extern "C" void kernel_launch(void* const* d_in, const int* in_sizes, int n_in,
                              void* d_out, int out_size) {
    const float* x   = (const float*)d_in[0];
    const float* W1  = (const float*)d_in[1];
    const float* b1  = (const float*)d_in[2];
    const float* W2  = (const float*)d_in[3];
    const float* b2  = (const float*)d_in[4];
    const float* Wfc = (const float*)d_in[5];
    const float* bfc = (const float*)d_in[6];
    float* out = (float*)d_out;

    int nimg = in_sizes[0] / 784;
    int npairs = nimg / 2;
    int ctas = (npairs + WARPS_PER_CTA - 1) / WARPS_PER_CTA;

    cudaFuncSetAttribute(diffsol_fused_kernel,
                         cudaFuncAttributeMaxDynamicSharedMemorySize, SMEM_BYTES);
    diffsol_fused_kernel<<<ctas, CTA_THREADS, SMEM_BYTES>>>(
        x, W1, b1, W2, b2, Wfc, bfc, out, npairs);
}